// round 16
// baseline (speedup 1.0000x reference)
#include <cuda_runtime.h>
#include <cuda_fp16.h>
#include <math.h>

#define NMAX 50048
#define EMAX 1000000

// ---------------- scratch (no allocations allowed) ----------------
__device__ int   g_src[EMAX];
__device__ int   g_dst[EMAX];
__device__ int   g_col[EMAX];
__device__ int   g_rowptr[NMAX + 1];
__device__ int   g_deg[NMAX];
__device__ int   g_cur[NMAX];
__device__ int   g_part[64];
__device__ int   g_flag;   // 1 => edge_index is int32, 0 => int64
__device__ float   g_h [(size_t)NMAX * 128];
__device__ float   g_xl[(size_t)NMAX * 128];
__device__ __half2 g_xrh[(size_t)NMAX * 64];   // xr in fp16 (gather payload)

__device__ __forceinline__ float f2tf32(float f) {
    unsigned u; asm("cvt.rna.tf32.f32 %0, %1;" : "=r"(u) : "f"(f));
    return __uint_as_float(u);
}

// gather 4 channels of xr (fp16) for node s, lane owns channels lane*4..+3
__device__ __forceinline__ float4 ldxr_h(int s, int lane) {
    uint2 u = *reinterpret_cast<const uint2*>(&g_xrh[(size_t)s * 64 + lane * 2]);
    __half2 h0 = *reinterpret_cast<__half2*>(&u.x);
    __half2 h1 = *reinterpret_cast<__half2*>(&u.y);
    float2 f0 = __half22float2(h0);
    float2 f1 = __half22float2(h1);
    return make_float4(f0.x, f0.y, f1.x, f1.y);
}

// ---------------- zero counters + edge dtype detection ----------------
__global__ void zero_detect(const void* ei, int e, int n) {
    int i = blockIdx.x * blockDim.x + threadIdx.x;
    if (i < n) { g_deg[i] = 0; g_cur[i] = 0; }
    if (blockIdx.x == 0) {
        __shared__ int any;
        if (threadIdx.x == 0) any = 0;
        __syncthreads();
        const int* w = (const int*)ei;
        int lim = 2048 < e ? 2048 : e;
        for (int k = threadIdx.x; k < lim; k += 256)
            if (w[2 * k + 1] != 0) any = 1;
        __syncthreads();
        if (threadIdx.x == 0) g_flag = any;
    }
}

// convert + degree histogram fused
__global__ void convert_hist(const void* ei, int e) {
    int i = blockIdx.x * blockDim.x + threadIdx.x;
    if (i >= e) return;
    int s, d;
    if (g_flag == 0) {
        const long long* p = (const long long*)ei;
        s = (int)p[i]; d = (int)p[e + i];
    } else {
        const int* p = (const int*)ei;
        s = p[i]; d = p[e + i];
    }
    g_src[i] = s;
    g_dst[i] = d;
    atomicAdd(&g_deg[d], 1);
}

// ---------------- scan phase 1: per-1024-block totals ----------------
__global__ __launch_bounds__(256) void scan_part(int n) {
    __shared__ int wsum[8];
    int b = blockIdx.x, t = threadIdx.x;
    int base = b * 1024 + t * 4;
    int s = 0;
    #pragma unroll
    for (int j = 0; j < 4; ++j) s += (base + j < n) ? g_deg[base + j] : 0;
    #pragma unroll
    for (int o = 16; o; o >>= 1) s += __shfl_xor_sync(0xffffffffu, s, o);
    if ((t & 31) == 0) wsum[t >> 5] = s;
    __syncthreads();
    if (t == 0) {
        int tot = 0;
        #pragma unroll
        for (int w = 0; w < 8; ++w) tot += wsum[w];
        g_part[b] = tot;
    }
}

// ---------------- scan phase 2: block scan + inline top prefix --------
__global__ __launch_bounds__(256) void scan_down(int n, int P) {
    __shared__ int wsum[8];
    __shared__ int s_off, s_tot;
    int b = blockIdx.x, t = threadIdx.x;
    int lane = t & 31;
    if (t < 32) {
        int v0 = (lane < P) ? g_part[lane] : 0;
        int v1 = (lane + 32 < P) ? g_part[lane + 32] : 0;
        int sb = ((lane < b) ? v0 : 0) + ((lane + 32 < b) ? v1 : 0);
        int sa = v0 + v1;
        #pragma unroll
        for (int o = 16; o; o >>= 1) {
            sb += __shfl_xor_sync(0xffffffffu, sb, o);
            sa += __shfl_xor_sync(0xffffffffu, sa, o);
        }
        if (lane == 0) { s_off = sb; s_tot = sa; }
    }
    int base = b * 1024 + t * 4;
    int v[4];
    #pragma unroll
    for (int j = 0; j < 4; ++j) v[j] = (base + j < n) ? g_deg[base + j] : 0;
    int s = v[0] + v[1] + v[2] + v[3];
    int incl = s;
    #pragma unroll
    for (int o = 1; o < 32; o <<= 1) {
        int u = __shfl_up_sync(0xffffffffu, incl, o);
        if (lane >= o) incl += u;
    }
    if (lane == 31) wsum[t >> 5] = incl;
    __syncthreads();
    int woff = 0;
    int myw = t >> 5;
    #pragma unroll
    for (int w = 0; w < 8; ++w) if (w < myw) woff += wsum[w];
    int run = s_off + woff + (incl - s);
    #pragma unroll
    for (int j = 0; j < 4; ++j) {
        if (base + j < n) g_rowptr[base + j] = run;
        run += v[j];
    }
    if (b == gridDim.x - 1 && t == 0) g_rowptr[n] = s_tot;
}

__global__ void scatter_edges(int e) {
    int i = blockIdx.x * blockDim.x + threadIdx.x;
    if (i >= e) return;
    int d = g_dst[i];
    int pos = g_rowptr[d] + atomicAdd(&g_cur[d], 1);
    g_col[pos] = i;   // edge id, for deterministic ordering
}

// warp-per-node rank sort of edge ids (unique), then map to src
__global__ __launch_bounds__(256) void sort_warp(int n) {
    int gw = (blockIdx.x * blockDim.x + threadIdx.x) >> 5;
    int lane = threadIdx.x & 31;
    if (gw >= n) return;
    int b = g_rowptr[gw], e = g_rowptr[gw + 1];
    int d = e - b;
    if (d <= 1) {
        if (d == 1 && lane == 0) g_col[b] = g_src[g_col[b]];
        return;
    }
    if (d <= 32) {
        int val = (lane < d) ? g_col[b + lane] : 0x7fffffff;
        int rank = 0;
        for (int j = 0; j < d; ++j) {
            int vj = __shfl_sync(0xffffffffu, val, j);
            rank += (vj < val);
        }
        if (lane < d) g_col[b + rank] = g_src[val];
    } else if (d <= 64) {
        int v0 = (lane < d)      ? g_col[b + lane]      : 0x7fffffff;
        int v1 = (32 + lane < d) ? g_col[b + 32 + lane] : 0x7fffffff;
        int r0 = 0, r1 = 0;
        for (int j = 0; j < d; ++j) {
            int vj = (j < 32) ? __shfl_sync(0xffffffffu, v0, j)
                              : __shfl_sync(0xffffffffu, v1, j - 32);
            r0 += (vj < v0);
            r1 += (vj < v1);
        }
        if (lane < d)      g_col[b + r0] = g_src[v0];
        if (32 + lane < d) g_col[b + r1] = g_src[v1];
    } else {
        if (lane == 0) {
            for (int k = b + 1; k < e; ++k) {
                int v = g_col[k];
                int j = k - 1;
                while (j >= b && g_col[j] > v) { g_col[j + 1] = g_col[j]; --j; }
                g_col[j + 1] = v;
            }
            for (int k = b; k < e; ++k) g_col[k] = g_src[g_col[k]];
        }
    }
}

// ---------------- FUSED: h = gelu(x@W_in+b_in) in smem (scalar FFMA),
//                  then xl = h@Wl+bl (fp32), xr = h@Wr+br (fp16), K=32 mma.
#define FUSED_SMEM (16384 + 32768 + 17408 + 17408)
__global__ __launch_bounds__(256) void fused_in_l0(
    const float* __restrict__ x, const float* __restrict__ Wi_g,
    const float* __restrict__ bi,
    const float* __restrict__ Wl, const float* __restrict__ bl,
    const float* __restrict__ Wr, const float* __restrict__ br,
    float* __restrict__ xl_out, int n)
{
    extern __shared__ char smraw[];
    float* Wi = (float*)smraw;                                    // [128*32]
    float (*xs)[128] = (float(*)[128])(smraw + 16384);            // [64][128]
    float (*hT)[136] = (float(*)[136])(smraw + 16384 + 32768);    // [32][136] k-major
    float (*BT)[136] = (float(*)[136])(smraw + 16384 + 32768 + 17408); // [32][136]

    int tid = threadIdx.x, warp = tid >> 5, lane = tid & 31;
    int node0 = blockIdx.x * 128;

    for (int i = tid; i < 1024; i += 256)
        *reinterpret_cast<float4*>(&Wi[i * 4]) = *reinterpret_cast<const float4*>(&Wi_g[i * 4]);

    const float is2 = 0.70710678118654752f;
    float bb_in = __ldg(&bi[lane]);

    for (int half = 0; half < 2; ++half) {
        __syncthreads();
        int base = node0 + half * 64;
        for (int i = tid; i < 64 * 32; i += 256) {
            int r = i >> 5, k4 = i & 31;
            int row = base + r;
            float4 v = make_float4(0.f, 0.f, 0.f, 0.f);
            if (row < n) v = *reinterpret_cast<const float4*>(&x[(size_t)row * 128 + k4 * 4]);
            *reinterpret_cast<float4*>(&xs[r][k4 * 4]) = v;
        }
        __syncthreads();
        int r0 = warp * 8;
        float acc[8];
        #pragma unroll
        for (int r = 0; r < 8; ++r) acc[r] = 0.f;
        #pragma unroll 4
        for (int k4 = 0; k4 < 32; ++k4) {
            float w0 = Wi[(k4 * 4 + 0) * 32 + lane];
            float w1 = Wi[(k4 * 4 + 1) * 32 + lane];
            float w2 = Wi[(k4 * 4 + 2) * 32 + lane];
            float w3 = Wi[(k4 * 4 + 3) * 32 + lane];
            #pragma unroll
            for (int r = 0; r < 8; ++r) {
                float4 xv = *reinterpret_cast<const float4*>(&xs[r0 + r][k4 * 4]);
                acc[r] = fmaf(xv.x, w0, fmaf(xv.y, w1, fmaf(xv.z, w2, fmaf(xv.w, w3, acc[r]))));
            }
        }
        #pragma unroll
        for (int r = 0; r < 8; ++r) {
            float a = acc[r] + bb_in;
            float gl = 0.5f * a * (1.f + erff(a * is2));
            hT[lane][half * 64 + r0 + r] = f2tf32(gl);
        }
    }

    __syncthreads();
    for (int i = tid; i < 32 * 128; i += 256) {
        int k = i >> 7, c = i & 127;
        BT[k][c] = f2tf32(Wl[i]);
    }
    __syncthreads();

    int g = lane >> 2, tig = lane & 3;
    int warp_m = warp & 3, warp_n = warp >> 2;

    for (int pass = 0; pass < 2; ++pass) {
        float macc[2][8][4];
        #pragma unroll
        for (int mt = 0; mt < 2; ++mt)
            #pragma unroll
            for (int nt = 0; nt < 8; ++nt)
                #pragma unroll
                for (int q = 0; q < 4; ++q) macc[mt][nt][q] = 0.f;

        #pragma unroll
        for (int ks = 0; ks < 4; ++ks) {
            int kb = ks * 8;
            unsigned af[2][4];
            #pragma unroll
            for (int mt = 0; mt < 2; ++mt) {
                int mr = warp_m * 32 + mt * 16;
                af[mt][0] = __float_as_uint(hT[kb + tig    ][mr + g]);
                af[mt][1] = __float_as_uint(hT[kb + tig    ][mr + g + 8]);
                af[mt][2] = __float_as_uint(hT[kb + tig + 4][mr + g]);
                af[mt][3] = __float_as_uint(hT[kb + tig + 4][mr + g + 8]);
            }
            #pragma unroll
            for (int nt = 0; nt < 8; ++nt) {
                int nc = warp_n * 64 + nt * 8;
                unsigned bf0 = __float_as_uint(BT[kb + tig    ][nc + g]);
                unsigned bf1 = __float_as_uint(BT[kb + tig + 4][nc + g]);
                #pragma unroll
                for (int mt = 0; mt < 2; ++mt) {
                    asm volatile(
                        "mma.sync.aligned.m16n8k8.row.col.f32.tf32.tf32.f32 "
                        "{%0,%1,%2,%3}, {%4,%5,%6,%7}, {%8,%9}, {%0,%1,%2,%3};"
                        : "+f"(macc[mt][nt][0]), "+f"(macc[mt][nt][1]),
                          "+f"(macc[mt][nt][2]), "+f"(macc[mt][nt][3])
                        : "r"(af[mt][0]), "r"(af[mt][1]), "r"(af[mt][2]), "r"(af[mt][3]),
                          "r"(bf0), "r"(bf1));
                }
            }
        }

        const float* bias = pass ? br : bl;
        #pragma unroll
        for (int nt = 0; nt < 8; ++nt) {
            int col = warp_n * 64 + nt * 8 + 2 * tig;
            float2 bb = *reinterpret_cast<const float2*>(&bias[col]);
            #pragma unroll
            for (int mt = 0; mt < 2; ++mt) {
                int row_a = node0 + warp_m * 32 + mt * 16 + g;
                int row_b = row_a + 8;
                float c0 = macc[mt][nt][0] + bb.x;
                float c1 = macc[mt][nt][1] + bb.y;
                float c2 = macc[mt][nt][2] + bb.x;
                float c3 = macc[mt][nt][3] + bb.y;
                if (pass == 0) {
                    if (row_a < n)
                        *reinterpret_cast<float2*>(&xl_out[(size_t)row_a * 128 + col]) = make_float2(c0, c1);
                    if (row_b < n)
                        *reinterpret_cast<float2*>(&xl_out[(size_t)row_b * 128 + col]) = make_float2(c2, c3);
                } else {
                    if (row_a < n) g_xrh[(size_t)row_a * 64 + (col >> 1)] = __floats2half2_rn(c0, c1);
                    if (row_b < n) g_xrh[(size_t)row_b * 64 + (col >> 1)] = __floats2half2_rn(c2, c3);
                }
            }
        }
        if (pass == 0) {
            __syncthreads();
            for (int i = tid; i < 32 * 128; i += 256) {
                int k = i >> 7, c = i & 127;
                BT[k][c] = f2tf32(Wr[i]);
            }
            __syncthreads();
        }
    }
}

// ---------------- TF32 tensor-core GEMM (dual): xl/xr, K=128 layers ----
// rowbase: starting row of this launch's slice (128-aligned)
__global__ __launch_bounds__(256) void gemm_mma(
    const float* __restrict__ A,
    const float* __restrict__ W0, const float* __restrict__ b0, float* __restrict__ C0,
    const float* __restrict__ W1, const float* __restrict__ b1,
    int n, int K, int rowbase)
{
    const float* W    = blockIdx.y ? W1 : W0;
    const float* bias = blockIdx.y ? b1 : b0;

    __shared__ float As[2][16][136];   // [k][m]
    __shared__ float Ws[2][16][136];   // [k][n]
    int tid  = threadIdx.x;
    int warp = tid >> 5, lane = tid & 31;
    int g    = lane >> 2, tig = lane & 3;
    int warp_m = warp & 3, warp_n = warp >> 2;
    int row0 = rowbase + blockIdx.x * 128;

    float acc[2][8][4];
    #pragma unroll
    for (int mt = 0; mt < 2; ++mt)
        #pragma unroll
        for (int nt = 0; nt < 8; ++nt)
            #pragma unroll
            for (int q = 0; q < 4; ++q) acc[mt][nt][q] = 0.f;

    int chunks = K >> 4;
    float4 ra[2], rw[2];

    #pragma unroll
    for (int j = 0; j < 2; ++j) {
        int idx = tid * 2 + j;
        int r = idx >> 2, k4 = idx & 3;
        ra[j] = *reinterpret_cast<const float4*>(&A[(size_t)(row0 + r) * K + k4 * 4]);
        int k = idx >> 5, c4 = idx & 31;
        rw[j] = *reinterpret_cast<const float4*>(&W[(size_t)k * 128 + c4 * 4]);
    }
    #pragma unroll
    for (int j = 0; j < 2; ++j) {
        int idx = tid * 2 + j;
        int r = idx >> 2, k4 = idx & 3;
        As[0][k4 * 4 + 0][r] = f2tf32(ra[j].x);
        As[0][k4 * 4 + 1][r] = f2tf32(ra[j].y);
        As[0][k4 * 4 + 2][r] = f2tf32(ra[j].z);
        As[0][k4 * 4 + 3][r] = f2tf32(ra[j].w);
        int k = idx >> 5, c4 = idx & 31;
        Ws[0][k][c4 * 4 + 0] = f2tf32(rw[j].x);
        Ws[0][k][c4 * 4 + 1] = f2tf32(rw[j].y);
        Ws[0][k][c4 * 4 + 2] = f2tf32(rw[j].z);
        Ws[0][k][c4 * 4 + 3] = f2tf32(rw[j].w);
    }
    __syncthreads();

    for (int c = 0; c < chunks; ++c) {
        int buf = c & 1;
        if (c + 1 < chunks) {
            int kc = (c + 1) * 16;
            #pragma unroll
            for (int j = 0; j < 2; ++j) {
                int idx = tid * 2 + j;
                int r = idx >> 2, k4 = idx & 3;
                ra[j] = *reinterpret_cast<const float4*>(&A[(size_t)(row0 + r) * K + kc + k4 * 4]);
                int k = idx >> 5, c4 = idx & 31;
                rw[j] = *reinterpret_cast<const float4*>(&W[(size_t)(kc + k) * 128 + c4 * 4]);
            }
        }
        #pragma unroll
        for (int ks = 0; ks < 2; ++ks) {
            int kb = ks * 8;
            unsigned af[2][4];
            #pragma unroll
            for (int mt = 0; mt < 2; ++mt) {
                int mr = warp_m * 32 + mt * 16;
                af[mt][0] = __float_as_uint(As[buf][kb + tig    ][mr + g]);
                af[mt][1] = __float_as_uint(As[buf][kb + tig    ][mr + g + 8]);
                af[mt][2] = __float_as_uint(As[buf][kb + tig + 4][mr + g]);
                af[mt][3] = __float_as_uint(As[buf][kb + tig + 4][mr + g + 8]);
            }
            #pragma unroll
            for (int nt = 0; nt < 8; ++nt) {
                int nc = warp_n * 64 + nt * 8;
                unsigned bf0 = __float_as_uint(Ws[buf][kb + tig    ][nc + g]);
                unsigned bf1 = __float_as_uint(Ws[buf][kb + tig + 4][nc + g]);
                #pragma unroll
                for (int mt = 0; mt < 2; ++mt) {
                    asm volatile(
                        "mma.sync.aligned.m16n8k8.row.col.f32.tf32.tf32.f32 "
                        "{%0,%1,%2,%3}, {%4,%5,%6,%7}, {%8,%9}, {%0,%1,%2,%3};"
                        : "+f"(acc[mt][nt][0]), "+f"(acc[mt][nt][1]),
                          "+f"(acc[mt][nt][2]), "+f"(acc[mt][nt][3])
                        : "r"(af[mt][0]), "r"(af[mt][1]), "r"(af[mt][2]), "r"(af[mt][3]),
                          "r"(bf0), "r"(bf1));
                }
            }
        }
        if (c + 1 < chunks) {
            int nb = buf ^ 1;
            #pragma unroll
            for (int j = 0; j < 2; ++j) {
                int idx = tid * 2 + j;
                int r = idx >> 2, k4 = idx & 3;
                As[nb][k4 * 4 + 0][r] = f2tf32(ra[j].x);
                As[nb][k4 * 4 + 1][r] = f2tf32(ra[j].y);
                As[nb][k4 * 4 + 2][r] = f2tf32(ra[j].z);
                As[nb][k4 * 4 + 3][r] = f2tf32(ra[j].w);
                int k = idx >> 5, c4 = idx & 31;
                Ws[nb][k][c4 * 4 + 0] = f2tf32(rw[j].x);
                Ws[nb][k][c4 * 4 + 1] = f2tf32(rw[j].y);
                Ws[nb][k][c4 * 4 + 2] = f2tf32(rw[j].z);
                Ws[nb][k][c4 * 4 + 3] = f2tf32(rw[j].w);
            }
        }
        __syncthreads();
    }

    int wantxl = (blockIdx.y == 0);
    #pragma unroll
    for (int nt = 0; nt < 8; ++nt) {
        int col = warp_n * 64 + nt * 8 + 2 * tig;
        float2 bb = *reinterpret_cast<const float2*>(&bias[col]);
        #pragma unroll
        for (int mt = 0; mt < 2; ++mt) {
            int row_a = row0 + warp_m * 32 + mt * 16 + g;
            int row_b = row_a + 8;
            float c0 = acc[mt][nt][0] + bb.x;
            float c1 = acc[mt][nt][1] + bb.y;
            float c2 = acc[mt][nt][2] + bb.x;
            float c3 = acc[mt][nt][3] + bb.y;
            if (wantxl) {
                if (row_a < n)
                    *reinterpret_cast<float2*>(&C0[(size_t)row_a * 128 + col]) = make_float2(c0, c1);
                if (row_b < n)
                    *reinterpret_cast<float2*>(&C0[(size_t)row_b * 128 + col]) = make_float2(c2, c3);
            } else {
                if (row_a < n)
                    g_xrh[(size_t)row_a * 64 + (col >> 1)] = __floats2half2_rn(c0, c1);
                if (row_b < n)
                    g_xrh[(size_t)row_b * 64 + (col >> 1)] = __floats2half2_rn(c2, c3);
            }
        }
    }
}

// ---------------- TF32 mma final projection with fused row L2 norm ----
__global__ __launch_bounds__(256) void gemm_out_mma(
    const float* __restrict__ A,
    const float* __restrict__ W, const float* __restrict__ bias,
    float* __restrict__ C, int n, int rowbase)
{
    __shared__ float As[2][16][136];
    __shared__ float Ws[2][16][136];
    __shared__ float rsum[128][2];
    const int K = 128;
    int tid  = threadIdx.x;
    int warp = tid >> 5, lane = tid & 31;
    int g    = lane >> 2, tig = lane & 3;
    int warp_m = warp & 3, warp_n = warp >> 2;
    int row0 = rowbase + blockIdx.x * 128;

    float acc[2][8][4];
    #pragma unroll
    for (int mt = 0; mt < 2; ++mt)
        #pragma unroll
        for (int nt = 0; nt < 8; ++nt)
            #pragma unroll
            for (int q = 0; q < 4; ++q) acc[mt][nt][q] = 0.f;

    int chunks = K >> 4;
    float4 ra[2], rw[2];
    #pragma unroll
    for (int j = 0; j < 2; ++j) {
        int idx = tid * 2 + j;
        int r = idx >> 2, k4 = idx & 3;
        ra[j] = *reinterpret_cast<const float4*>(&A[(size_t)(row0 + r) * K + k4 * 4]);
        int k = idx >> 5, c4 = idx & 31;
        rw[j] = *reinterpret_cast<const float4*>(&W[(size_t)k * 128 + c4 * 4]);
    }
    #pragma unroll
    for (int j = 0; j < 2; ++j) {
        int idx = tid * 2 + j;
        int r = idx >> 2, k4 = idx & 3;
        As[0][k4 * 4 + 0][r] = f2tf32(ra[j].x);
        As[0][k4 * 4 + 1][r] = f2tf32(ra[j].y);
        As[0][k4 * 4 + 2][r] = f2tf32(ra[j].z);
        As[0][k4 * 4 + 3][r] = f2tf32(ra[j].w);
        int k = idx >> 5, c4 = idx & 31;
        Ws[0][k][c4 * 4 + 0] = f2tf32(rw[j].x);
        Ws[0][k][c4 * 4 + 1] = f2tf32(rw[j].y);
        Ws[0][k][c4 * 4 + 2] = f2tf32(rw[j].z);
        Ws[0][k][c4 * 4 + 3] = f2tf32(rw[j].w);
    }
    __syncthreads();

    for (int c = 0; c < chunks; ++c) {
        int buf = c & 1;
        if (c + 1 < chunks) {
            int kc = (c + 1) * 16;
            #pragma unroll
            for (int j = 0; j < 2; ++j) {
                int idx = tid * 2 + j;
                int r = idx >> 2, k4 = idx & 3;
                ra[j] = *reinterpret_cast<const float4*>(&A[(size_t)(row0 + r) * K + kc + k4 * 4]);
                int k = idx >> 5, c4 = idx & 31;
                rw[j] = *reinterpret_cast<const float4*>(&W[(size_t)(kc + k) * 128 + c4 * 4]);
            }
        }
        #pragma unroll
        for (int ks = 0; ks < 2; ++ks) {
            int kb = ks * 8;
            unsigned af[2][4];
            #pragma unroll
            for (int mt = 0; mt < 2; ++mt) {
                int mr = warp_m * 32 + mt * 16;
                af[mt][0] = __float_as_uint(As[buf][kb + tig    ][mr + g]);
                af[mt][1] = __float_as_uint(As[buf][kb + tig    ][mr + g + 8]);
                af[mt][2] = __float_as_uint(As[buf][kb + tig + 4][mr + g]);
                af[mt][3] = __float_as_uint(As[buf][kb + tig + 4][mr + g + 8]);
            }
            #pragma unroll
            for (int nt = 0; nt < 8; ++nt) {
                int nc = warp_n * 64 + nt * 8;
                unsigned bf0 = __float_as_uint(Ws[buf][kb + tig    ][nc + g]);
                unsigned bf1 = __float_as_uint(Ws[buf][kb + tig + 4][nc + g]);
                #pragma unroll
                for (int mt = 0; mt < 2; ++mt) {
                    asm volatile(
                        "mma.sync.aligned.m16n8k8.row.col.f32.tf32.tf32.f32 "
                        "{%0,%1,%2,%3}, {%4,%5,%6,%7}, {%8,%9}, {%0,%1,%2,%3};"
                        : "+f"(acc[mt][nt][0]), "+f"(acc[mt][nt][1]),
                          "+f"(acc[mt][nt][2]), "+f"(acc[mt][nt][3])
                        : "r"(af[mt][0]), "r"(af[mt][1]), "r"(af[mt][2]), "r"(af[mt][3]),
                          "r"(bf0), "r"(bf1));
                }
            }
        }
        if (c + 1 < chunks) {
            int nb = buf ^ 1;
            #pragma unroll
            for (int j = 0; j < 2; ++j) {
                int idx = tid * 2 + j;
                int r = idx >> 2, k4 = idx & 3;
                As[nb][k4 * 4 + 0][r] = f2tf32(ra[j].x);
                As[nb][k4 * 4 + 1][r] = f2tf32(ra[j].y);
                As[nb][k4 * 4 + 2][r] = f2tf32(ra[j].z);
                As[nb][k4 * 4 + 3][r] = f2tf32(ra[j].w);
                int k = idx >> 5, c4 = idx & 31;
                Ws[nb][k][c4 * 4 + 0] = f2tf32(rw[j].x);
                Ws[nb][k][c4 * 4 + 1] = f2tf32(rw[j].y);
                Ws[nb][k][c4 * 4 + 2] = f2tf32(rw[j].z);
                Ws[nb][k][c4 * 4 + 3] = f2tf32(rw[j].w);
            }
        }
        __syncthreads();
    }

    float sa[2] = {0.f, 0.f}, sb[2] = {0.f, 0.f};
    #pragma unroll
    for (int nt = 0; nt < 8; ++nt) {
        int col = warp_n * 64 + nt * 8 + 2 * tig;
        float2 bb = *reinterpret_cast<const float2*>(&bias[col]);
        #pragma unroll
        for (int mt = 0; mt < 2; ++mt) {
            acc[mt][nt][0] += bb.x;
            acc[mt][nt][1] += bb.y;
            acc[mt][nt][2] += bb.x;
            acc[mt][nt][3] += bb.y;
            sa[mt] = fmaf(acc[mt][nt][0], acc[mt][nt][0], fmaf(acc[mt][nt][1], acc[mt][nt][1], sa[mt]));
            sb[mt] = fmaf(acc[mt][nt][2], acc[mt][nt][2], fmaf(acc[mt][nt][3], acc[mt][nt][3], sb[mt]));
        }
    }
    #pragma unroll
    for (int mt = 0; mt < 2; ++mt) {
        sa[mt] += __shfl_xor_sync(0xffffffffu, sa[mt], 1);
        sa[mt] += __shfl_xor_sync(0xffffffffu, sa[mt], 2);
        sb[mt] += __shfl_xor_sync(0xffffffffu, sb[mt], 1);
        sb[mt] += __shfl_xor_sync(0xffffffffu, sb[mt], 2);
        if (tig == 0) {
            int rla = warp_m * 32 + mt * 16 + g;
            rsum[rla][warp_n]     = sa[mt];
            rsum[rla + 8][warp_n] = sb[mt];
        }
    }
    __syncthreads();
    #pragma unroll
    for (int mt = 0; mt < 2; ++mt) {
        int rla = warp_m * 32 + mt * 16 + g;
        float inva = 1.f / fmaxf(sqrtf(rsum[rla][0]     + rsum[rla][1]),     1e-12f);
        float invb = 1.f / fmaxf(sqrtf(rsum[rla + 8][0] + rsum[rla + 8][1]), 1e-12f);
        int row_a = row0 + rla;
        int row_b = row_a + 8;
        #pragma unroll
        for (int nt = 0; nt < 8; ++nt) {
            int col = warp_n * 64 + nt * 8 + 2 * tig;
            if (row_a < n)
                *reinterpret_cast<float2*>(&C[(size_t)row_a * 128 + col]) =
                    make_float2(acc[mt][nt][0] * inva, acc[mt][nt][1] * inva);
            if (row_b < n)
                *reinterpret_cast<float2*>(&C[(size_t)row_b * 128 + col]) =
                    make_float2(acc[mt][nt][2] * invb, acc[mt][nt][3] * invb);
        }
    }
}

// ---------------- fused GATv2 aggregation + LayerNorm + GELU + residual
// ONE WARP per node in [i0, nend); dual-dot logit; 3-step shfl reduce.
__global__ __launch_bounds__(256) void gat_agg(
    const float* __restrict__ att, const float* __restrict__ bo,
    const float* __restrict__ gam, const float* __restrict__ bet,
    int resflag, int i0, int nend)
{
    int warp = threadIdx.x >> 5;
    int lane = threadIdx.x & 31;
    int i = i0 + blockIdx.x * 8 + warp;
    if (i >= nend) return;
    int c0 = lane * 4;

    float4 xl = *reinterpret_cast<const float4*>(&g_xl[(size_t)i * 128 + c0]);
    float4 a4 = __ldg(reinterpret_cast<const float4*>(&att[c0]));

#define GAT_LOGIT(vv, xv)                                                    \
    {                                                                        \
        float s0 = xl.x + xv.x;                                              \
        float s1 = xl.y + xv.y;                                              \
        float s2 = xl.z + xv.z;                                              \
        float s3 = xl.w + xv.w;                                              \
        float dA = s0 * a4.x;                                                \
        dA = fmaf(s1, a4.y, dA);                                             \
        dA = fmaf(s2, a4.z, dA);                                             \
        dA = fmaf(s3, a4.w, dA);                                             \
        float dB = fabsf(s0) * a4.x;                                         \
        dB = fmaf(fabsf(s1), a4.y, dB);                                      \
        dB = fmaf(fabsf(s2), a4.z, dB);                                      \
        dB = fmaf(fabsf(s3), a4.w, dB);                                      \
        vv = fmaf(0.4f, dB, 0.6f * dA);                                      \
    }

    // self loop first
    float4 xs = ldxr_h(i, lane);
    float v;
    GAT_LOGIT(v, xs);
    v += __shfl_xor_sync(0xffffffffu, v, 1);
    v += __shfl_xor_sync(0xffffffffu, v, 2);
    v += __shfl_xor_sync(0xffffffffu, v, 4);
    float m = v, den = 1.f;
    float4 acc = xs;

#define GAT_RUNMERGE(vv, xv)                                                 \
    {                                                                        \
        float nm = fmaxf(m, vv);                                             \
        float sc = __expf(m - nm);                                           \
        float pe = __expf(vv - nm);                                          \
        den = fmaf(den, sc, pe);                                             \
        acc.x = fmaf(acc.x, sc, pe * xv.x);                                  \
        acc.y = fmaf(acc.y, sc, pe * xv.y);                                  \
        acc.z = fmaf(acc.z, sc, pe * xv.z);                                  \
        acc.w = fmaf(acc.w, sc, pe * xv.w);                                  \
        m = nm;                                                              \
    }

#define GAT_BODY4(xa, xb, xc, xd)                                            \
    {                                                                        \
        float va, vb, vc, vd;                                                \
        GAT_LOGIT(va, xa);                                                   \
        GAT_LOGIT(vb, xb);                                                   \
        GAT_LOGIT(vc, xc);                                                   \
        GAT_LOGIT(vd, xd);                                                   \
        va += __shfl_xor_sync(0xffffffffu, va, 1);                           \
        vb += __shfl_xor_sync(0xffffffffu, vb, 1);                           \
        vc += __shfl_xor_sync(0xffffffffu, vc, 1);                           \
        vd += __shfl_xor_sync(0xffffffffu, vd, 1);                           \
        va += __shfl_xor_sync(0xffffffffu, va, 2);                           \
        vb += __shfl_xor_sync(0xffffffffu, vb, 2);                           \
        vc += __shfl_xor_sync(0xffffffffu, vc, 2);                           \
        vd += __shfl_xor_sync(0xffffffffu, vd, 2);                           \
        va += __shfl_xor_sync(0xffffffffu, va, 4);                           \
        vb += __shfl_xor_sync(0xffffffffu, vb, 4);                           \
        vc += __shfl_xor_sync(0xffffffffu, vc, 4);                           \
        vd += __shfl_xor_sync(0xffffffffu, vd, 4);                           \
        float mab = fmaxf(va, vb);                                           \
        float pa  = __expf(va - mab);                                        \
        float pb  = __expf(vb - mab);                                        \
        float dab = pa + pb;                                                 \
        float4 aab;                                                          \
        aab.x = fmaf(pa, xa.x, pb * xb.x);                                   \
        aab.y = fmaf(pa, xa.y, pb * xb.y);                                   \
        aab.z = fmaf(pa, xa.z, pb * xb.z);                                   \
        aab.w = fmaf(pa, xa.w, pb * xb.w);                                   \
        float mcd = fmaxf(vc, vd);                                           \
        float pc  = __expf(vc - mcd);                                        \
        float pd  = __expf(vd - mcd);                                        \
        float dcd = pc + pd;                                                 \
        float4 acd;                                                          \
        acd.x = fmaf(pc, xc.x, pd * xd.x);                                   \
        acd.y = fmaf(pc, xc.y, pd * xd.y);                                   \
        acd.z = fmaf(pc, xc.z, pd * xd.z);                                   \
        acd.w = fmaf(pc, xc.w, pd * xd.w);                                   \
        {                                                                    \
            float nm = fmaxf(m, mab);                                        \
            float sc = __expf(m - nm);                                       \
            float s2 = __expf(mab - nm);                                     \
            den = fmaf(den, sc, dab * s2);                                   \
            acc.x = fmaf(acc.x, sc, aab.x * s2);                             \
            acc.y = fmaf(acc.y, sc, aab.y * s2);                             \
            acc.z = fmaf(acc.z, sc, aab.z * s2);                             \
            acc.w = fmaf(acc.w, sc, aab.w * s2);                             \
            m = nm;                                                          \
        }                                                                    \
        {                                                                    \
            float nm = fmaxf(m, mcd);                                        \
            float sc = __expf(m - nm);                                       \
            float s2 = __expf(mcd - nm);                                     \
            den = fmaf(den, sc, dcd * s2);                                   \
            acc.x = fmaf(acc.x, sc, acd.x * s2);                             \
            acc.y = fmaf(acc.y, sc, acd.y * s2);                             \
            acc.z = fmaf(acc.z, sc, acd.z * s2);                             \
            acc.w = fmaf(acc.w, sc, acd.w * s2);                             \
            m = nm;                                                          \
        }                                                                    \
    }

    int beg = g_rowptr[i], end = g_rowptr[i + 1];
    int k = beg;

    float4 pxa, pxb, pxc, pxd;
    if (k + 4 <= end) {
        pxa = ldxr_h(g_col[k], lane);
        pxb = ldxr_h(g_col[k + 1], lane);
        pxc = ldxr_h(g_col[k + 2], lane);
        pxd = ldxr_h(g_col[k + 3], lane);
    }
    for (; k + 8 <= end; k += 4) {
        float4 nxa = ldxr_h(g_col[k + 4], lane);
        float4 nxb = ldxr_h(g_col[k + 5], lane);
        float4 nxc = ldxr_h(g_col[k + 6], lane);
        float4 nxd = ldxr_h(g_col[k + 7], lane);
        GAT_BODY4(pxa, pxb, pxc, pxd);
        pxa = nxa; pxb = nxb; pxc = nxc; pxd = nxd;
    }
    if (k + 4 <= end) {
        GAT_BODY4(pxa, pxb, pxc, pxd);
        k += 4;
    }
    if (k + 2 <= end) {
        float4 xa = ldxr_h(g_col[k], lane);
        float4 xb = ldxr_h(g_col[k + 1], lane);
        float va, vb;
        GAT_LOGIT(va, xa);
        GAT_LOGIT(vb, xb);
        va += __shfl_xor_sync(0xffffffffu, va, 1);
        vb += __shfl_xor_sync(0xffffffffu, vb, 1);
        va += __shfl_xor_sync(0xffffffffu, va, 2);
        vb += __shfl_xor_sync(0xffffffffu, vb, 2);
        va += __shfl_xor_sync(0xffffffffu, va, 4);
        vb += __shfl_xor_sync(0xffffffffu, vb, 4);
        GAT_RUNMERGE(va, xa);
        GAT_RUNMERGE(vb, xb);
        k += 2;
    }
    if (k < end) {
        float4 xa = ldxr_h(g_col[k], lane);
        float va;
        GAT_LOGIT(va, xa);
        va += __shfl_xor_sync(0xffffffffu, va, 1);
        va += __shfl_xor_sync(0xffffffffu, va, 2);
        va += __shfl_xor_sync(0xffffffffu, va, 4);
        GAT_RUNMERGE(va, xa);
    }
#undef GAT_LOGIT
#undef GAT_RUNMERGE
#undef GAT_BODY4

    float inv = 1.f / (den + 1e-16f);
    float4 bo4 = __ldg(reinterpret_cast<const float4*>(&bo[c0]));
    float o0 = fmaf(acc.x, inv, bo4.x);
    float o1 = fmaf(acc.y, inv, bo4.y);
    float o2 = fmaf(acc.z, inv, bo4.z);
    float o3 = fmaf(acc.w, inv, bo4.w);

    float s1 = o0 + o1 + o2 + o3;
    float s2 = fmaf(o0, o0, fmaf(o1, o1, fmaf(o2, o2, o3 * o3)));
    #pragma unroll
    for (int o = 1; o < 32; o <<= 1) {
        s1 += __shfl_xor_sync(0xffffffffu, s1, o);
        s2 += __shfl_xor_sync(0xffffffffu, s2, o);
    }
    float mu  = s1 * (1.f / 128.f);
    float var = s2 * (1.f / 128.f) - mu * mu;
    var = var > 0.f ? var : 0.f;
    float rstd = rsqrtf(var + 1e-5f);
    float4 g4 = __ldg(reinterpret_cast<const float4*>(&gam[c0]));
    float4 b4 = __ldg(reinterpret_cast<const float4*>(&bet[c0]));
    float y0 = g4.x * (o0 - mu) * rstd + b4.x;
    float y1 = g4.y * (o1 - mu) * rstd + b4.y;
    float y2 = g4.z * (o2 - mu) * rstd + b4.z;
    float y3 = g4.w * (o3 - mu) * rstd + b4.w;
    const float is2 = 0.70710678118654752f;
    float gl0 = 0.5f * y0 * (1.f + erff(y0 * is2));
    float gl1 = 0.5f * y1 * (1.f + erff(y1 * is2));
    float gl2 = 0.5f * y2 * (1.f + erff(y2 * is2));
    float gl3 = 0.5f * y3 * (1.f + erff(y3 * is2));

    float4* hp = reinterpret_cast<float4*>(&g_h[(size_t)i * 128 + c0]);
    if (resflag) {
        float4 hv = *hp;
        hv.x += gl0; hv.y += gl1; hv.z += gl2; hv.w += gl3;
        *hp = hv;
    } else {
        *hp = make_float4(gl0, gl1, gl2, gl3);
    }
}

// ---------------- host launcher ----------------
extern "C" void kernel_launch(void* const* d_in, const int* in_sizes, int n_in,
                              void* d_out, int out_size)
{
    const float* x    = (const float*)d_in[0];
    const void*  ei   = d_in[1];
    const float* W_in = (const float*)d_in[2];
    const float* b_in = (const float*)d_in[3];
    const float *Wl[3], *bl[3], *Wr[3], *br[3], *att[3], *bo[3], *gg[3], *be[3];
    for (int l = 0; l < 3; ++l) {
        int base = 4 + l * 8;
        Wl[l]  = (const float*)d_in[base + 0];
        bl[l]  = (const float*)d_in[base + 1];
        Wr[l]  = (const float*)d_in[base + 2];
        br[l]  = (const float*)d_in[base + 3];
        att[l] = (const float*)d_in[base + 4];
        bo[l]  = (const float*)d_in[base + 5];
        gg[l]  = (const float*)d_in[base + 6];
        be[l]  = (const float*)d_in[base + 7];
    }
    const float* W_out = (const float*)d_in[28];
    const float* b_out = (const float*)d_in[29];

    int n = in_sizes[0] / 128;
    int e = in_sizes[1] / 2;
    int P = (n + 1023) / 1024;

    float *hbuf, *xlbuf;
    cudaGetSymbolAddress((void**)&hbuf,  g_h);
    cudaGetSymbolAddress((void**)&xlbuf, g_xl);

    static int inited = 0;
    static cudaStream_t s2;
    static cudaEvent_t ev_fork, ev_csr;
    static cudaEvent_t ev_pre[3], ev_g1[3];
    if (!inited) {
        cudaFuncSetAttribute(fused_in_l0,
                             cudaFuncAttributeMaxDynamicSharedMemorySize, FUSED_SMEM);
        cudaStreamCreateWithFlags(&s2, cudaStreamNonBlocking);
        cudaEventCreateWithFlags(&ev_fork, cudaEventDisableTiming);
        cudaEventCreateWithFlags(&ev_csr, cudaEventDisableTiming);
        for (int l = 0; l < 3; ++l) {
            cudaEventCreateWithFlags(&ev_pre[l], cudaEventDisableTiming);
            cudaEventCreateWithFlags(&ev_g1[l], cudaEventDisableTiming);
        }
        inited = 1;
    }

    int gsingle = (n + 127) / 128;

    // node split (128-aligned) for gat/gemm pipelining
    int nh = ((n / 2) + 127) & ~127;
    if (nh > n) nh = n;
    int gb0 = nh / 128;
    int gb1 = gsingle - gb0;
    int ab0 = (nh + 7) / 8;
    int ab1 = (n - nh + 7) / 8;

    // fork: CSR chain on s2, concurrent with fused_in_l0 on main stream
    cudaEventRecord(ev_fork, 0);
    cudaStreamWaitEvent(s2, ev_fork, 0);

    zero_detect<<<(n + 255) / 256, 256, 0, s2>>>(ei, e, n);
    convert_hist<<<(e + 255) / 256, 256, 0, s2>>>(ei, e);
    scan_part<<<P, 256, 0, s2>>>(n);
    scan_down<<<P, 256, 0, s2>>>(n, P);
    scatter_edges<<<(e + 255) / 256, 256, 0, s2>>>(e);
    sort_warp<<<(n + 7) / 8, 256, 0, s2>>>(n);
    cudaEventRecord(ev_csr, s2);

    fused_in_l0<<<gsingle, 256, FUSED_SMEM>>>(x, W_in, b_in,
                                              Wl[0], bl[0], Wr[0], br[0],
                                              xlbuf, n);
    cudaStreamWaitEvent(0, ev_csr, 0);

    // layers with half-split gat/gemm pipelining
    for (int l = 0; l < 3; ++l) {
        int rf = (l > 0) ? 1 : 0;
        // fork: half1 gat on s2 (prereqs = everything on main so far)
        cudaEventRecord(ev_pre[l], 0);
        cudaStreamWaitEvent(s2, ev_pre[l], 0);
        if (ab1 > 0)
            gat_agg<<<ab1, 256, 0, s2>>>(att[l], bo[l], gg[l], be[l], rf, nh, n);
        cudaEventRecord(ev_g1[l], s2);

        // main: half0 gat, then next-op on half0 rows
        gat_agg<<<ab0, 256>>>(att[l], bo[l], gg[l], be[l], rf, 0, nh);

        if (l < 2) {
            gemm_mma<<<dim3(gb0, 2), 256>>>(hbuf, Wl[l + 1], bl[l + 1], xlbuf,
                                            Wr[l + 1], br[l + 1], n, 128, 0);
            cudaStreamWaitEvent(0, ev_g1[l], 0);
            if (gb1 > 0)
                gemm_mma<<<dim3(gb1, 2), 256>>>(hbuf, Wl[l + 1], bl[l + 1], xlbuf,
                                                Wr[l + 1], br[l + 1], n, 128, nh);
        } else {
            gemm_out_mma<<<gb0, 256>>>(hbuf, W_out, b_out, (float*)d_out, n, 0);
            cudaStreamWaitEvent(0, ev_g1[l], 0);
            if (gb1 > 0)
                gemm_out_mma<<<gb1, 256>>>(hbuf, W_out, b_out, (float*)d_out, n, nh);
        }
    }
}

// round 17
// speedup vs baseline: 1.0486x; 1.0486x over previous
#include <cuda_runtime.h>
#include <cuda_fp16.h>
#include <math.h>

#define NMAX 50048
#define EMAX 1000000

// ---------------- scratch (no allocations allowed) ----------------
__device__ int   g_src[EMAX];
__device__ int   g_dst[EMAX];
__device__ int   g_col[EMAX];
__device__ int   g_rowptr[NMAX + 1];
__device__ int   g_deg[NMAX];
__device__ int   g_cur[NMAX];
__device__ int   g_part[64];
__device__ int   g_flag;   // 1 => edge_index is int32, 0 => int64
__device__ float   g_h [(size_t)NMAX * 128];
__device__ float   g_xl[(size_t)NMAX * 128];
__device__ __half2 g_xrh[(size_t)NMAX * 64];   // xr in fp16 (gather payload)

__device__ __forceinline__ float f2tf32(float f) {
    unsigned u; asm("cvt.rna.tf32.f32 %0, %1;" : "=r"(u) : "f"(f));
    return __uint_as_float(u);
}

// gather 4 channels of xr (fp16) for node s, lane owns channels lane*4..+3
__device__ __forceinline__ float4 ldxr_h(int s, int lane) {
    uint2 u = *reinterpret_cast<const uint2*>(&g_xrh[(size_t)s * 64 + lane * 2]);
    __half2 h0 = *reinterpret_cast<__half2*>(&u.x);
    __half2 h1 = *reinterpret_cast<__half2*>(&u.y);
    float2 f0 = __half22float2(h0);
    float2 f1 = __half22float2(h1);
    return make_float4(f0.x, f0.y, f1.x, f1.y);
}

// ---------------- zero counters + edge dtype detection ----------------
__global__ void zero_detect(const void* ei, int e, int n) {
    int i = blockIdx.x * blockDim.x + threadIdx.x;
    if (i < n) { g_deg[i] = 0; g_cur[i] = 0; }
    if (blockIdx.x == 0) {
        __shared__ int any;
        if (threadIdx.x == 0) any = 0;
        __syncthreads();
        const int* w = (const int*)ei;
        int lim = 2048 < e ? 2048 : e;
        for (int k = threadIdx.x; k < lim; k += 256)
            if (w[2 * k + 1] != 0) any = 1;
        __syncthreads();
        if (threadIdx.x == 0) g_flag = any;
    }
}

// convert + degree histogram fused
__global__ void convert_hist(const void* ei, int e) {
    int i = blockIdx.x * blockDim.x + threadIdx.x;
    if (i >= e) return;
    int s, d;
    if (g_flag == 0) {
        const long long* p = (const long long*)ei;
        s = (int)p[i]; d = (int)p[e + i];
    } else {
        const int* p = (const int*)ei;
        s = p[i]; d = p[e + i];
    }
    g_src[i] = s;
    g_dst[i] = d;
    atomicAdd(&g_deg[d], 1);
}

// ---------------- scan phase 1: per-1024-block totals ----------------
__global__ __launch_bounds__(256) void scan_part(int n) {
    __shared__ int wsum[8];
    int b = blockIdx.x, t = threadIdx.x;
    int base = b * 1024 + t * 4;
    int s = 0;
    #pragma unroll
    for (int j = 0; j < 4; ++j) s += (base + j < n) ? g_deg[base + j] : 0;
    #pragma unroll
    for (int o = 16; o; o >>= 1) s += __shfl_xor_sync(0xffffffffu, s, o);
    if ((t & 31) == 0) wsum[t >> 5] = s;
    __syncthreads();
    if (t == 0) {
        int tot = 0;
        #pragma unroll
        for (int w = 0; w < 8; ++w) tot += wsum[w];
        g_part[b] = tot;
    }
}

// ---------------- scan phase 2: block scan + inline top prefix --------
__global__ __launch_bounds__(256) void scan_down(int n, int P) {
    __shared__ int wsum[8];
    __shared__ int s_off, s_tot;
    int b = blockIdx.x, t = threadIdx.x;
    int lane = t & 31;
    if (t < 32) {
        int v0 = (lane < P) ? g_part[lane] : 0;
        int v1 = (lane + 32 < P) ? g_part[lane + 32] : 0;
        int sb = ((lane < b) ? v0 : 0) + ((lane + 32 < b) ? v1 : 0);
        int sa = v0 + v1;
        #pragma unroll
        for (int o = 16; o; o >>= 1) {
            sb += __shfl_xor_sync(0xffffffffu, sb, o);
            sa += __shfl_xor_sync(0xffffffffu, sa, o);
        }
        if (lane == 0) { s_off = sb; s_tot = sa; }
    }
    int base = b * 1024 + t * 4;
    int v[4];
    #pragma unroll
    for (int j = 0; j < 4; ++j) v[j] = (base + j < n) ? g_deg[base + j] : 0;
    int s = v[0] + v[1] + v[2] + v[3];
    int incl = s;
    #pragma unroll
    for (int o = 1; o < 32; o <<= 1) {
        int u = __shfl_up_sync(0xffffffffu, incl, o);
        if (lane >= o) incl += u;
    }
    if (lane == 31) wsum[t >> 5] = incl;
    __syncthreads();
    int woff = 0;
    int myw = t >> 5;
    #pragma unroll
    for (int w = 0; w < 8; ++w) if (w < myw) woff += wsum[w];
    int run = s_off + woff + (incl - s);
    #pragma unroll
    for (int j = 0; j < 4; ++j) {
        if (base + j < n) g_rowptr[base + j] = run;
        run += v[j];
    }
    if (b == gridDim.x - 1 && t == 0) g_rowptr[n] = s_tot;
}

__global__ void scatter_edges(int e) {
    int i = blockIdx.x * blockDim.x + threadIdx.x;
    if (i >= e) return;
    int d = g_dst[i];
    int pos = g_rowptr[d] + atomicAdd(&g_cur[d], 1);
    g_col[pos] = i;   // edge id, for deterministic ordering
}

// warp-per-node rank sort of edge ids (unique), then map to src
__global__ __launch_bounds__(256) void sort_warp(int n) {
    int gw = (blockIdx.x * blockDim.x + threadIdx.x) >> 5;
    int lane = threadIdx.x & 31;
    if (gw >= n) return;
    int b = g_rowptr[gw], e = g_rowptr[gw + 1];
    int d = e - b;
    if (d <= 1) {
        if (d == 1 && lane == 0) g_col[b] = g_src[g_col[b]];
        return;
    }
    if (d <= 32) {
        int val = (lane < d) ? g_col[b + lane] : 0x7fffffff;
        int rank = 0;
        for (int j = 0; j < d; ++j) {
            int vj = __shfl_sync(0xffffffffu, val, j);
            rank += (vj < val);
        }
        if (lane < d) g_col[b + rank] = g_src[val];
    } else if (d <= 64) {
        int v0 = (lane < d)      ? g_col[b + lane]      : 0x7fffffff;
        int v1 = (32 + lane < d) ? g_col[b + 32 + lane] : 0x7fffffff;
        int r0 = 0, r1 = 0;
        for (int j = 0; j < d; ++j) {
            int vj = (j < 32) ? __shfl_sync(0xffffffffu, v0, j)
                              : __shfl_sync(0xffffffffu, v1, j - 32);
            r0 += (vj < v0);
            r1 += (vj < v1);
        }
        if (lane < d)      g_col[b + r0] = g_src[v0];
        if (32 + lane < d) g_col[b + r1] = g_src[v1];
    } else {
        if (lane == 0) {
            for (int k = b + 1; k < e; ++k) {
                int v = g_col[k];
                int j = k - 1;
                while (j >= b && g_col[j] > v) { g_col[j + 1] = g_col[j]; --j; }
                g_col[j + 1] = v;
            }
            for (int k = b; k < e; ++k) g_col[k] = g_src[g_col[k]];
        }
    }
}

// ---------------- FUSED: h = gelu(x@W_in+b_in) in smem (scalar FFMA),
//                  then xl = h@Wl+bl (fp32), xr = h@Wr+br (fp16), K=32 mma.
#define FUSED_SMEM (16384 + 32768 + 17408 + 17408)
__global__ __launch_bounds__(256) void fused_in_l0(
    const float* __restrict__ x, const float* __restrict__ Wi_g,
    const float* __restrict__ bi,
    const float* __restrict__ Wl, const float* __restrict__ bl,
    const float* __restrict__ Wr, const float* __restrict__ br,
    float* __restrict__ xl_out, int n)
{
    extern __shared__ char smraw[];
    float* Wi = (float*)smraw;                                    // [128*32]
    float (*xs)[128] = (float(*)[128])(smraw + 16384);            // [64][128]
    float (*hT)[136] = (float(*)[136])(smraw + 16384 + 32768);    // [32][136] k-major
    float (*BT)[136] = (float(*)[136])(smraw + 16384 + 32768 + 17408); // [32][136]

    int tid = threadIdx.x, warp = tid >> 5, lane = tid & 31;
    int node0 = blockIdx.x * 128;

    for (int i = tid; i < 1024; i += 256)
        *reinterpret_cast<float4*>(&Wi[i * 4]) = *reinterpret_cast<const float4*>(&Wi_g[i * 4]);

    const float is2 = 0.70710678118654752f;
    float bb_in = __ldg(&bi[lane]);

    for (int half = 0; half < 2; ++half) {
        __syncthreads();
        int base = node0 + half * 64;
        for (int i = tid; i < 64 * 32; i += 256) {
            int r = i >> 5, k4 = i & 31;
            int row = base + r;
            float4 v = make_float4(0.f, 0.f, 0.f, 0.f);
            if (row < n) v = *reinterpret_cast<const float4*>(&x[(size_t)row * 128 + k4 * 4]);
            *reinterpret_cast<float4*>(&xs[r][k4 * 4]) = v;
        }
        __syncthreads();
        int r0 = warp * 8;
        float acc[8];
        #pragma unroll
        for (int r = 0; r < 8; ++r) acc[r] = 0.f;
        #pragma unroll 4
        for (int k4 = 0; k4 < 32; ++k4) {
            float w0 = Wi[(k4 * 4 + 0) * 32 + lane];
            float w1 = Wi[(k4 * 4 + 1) * 32 + lane];
            float w2 = Wi[(k4 * 4 + 2) * 32 + lane];
            float w3 = Wi[(k4 * 4 + 3) * 32 + lane];
            #pragma unroll
            for (int r = 0; r < 8; ++r) {
                float4 xv = *reinterpret_cast<const float4*>(&xs[r0 + r][k4 * 4]);
                acc[r] = fmaf(xv.x, w0, fmaf(xv.y, w1, fmaf(xv.z, w2, fmaf(xv.w, w3, acc[r]))));
            }
        }
        #pragma unroll
        for (int r = 0; r < 8; ++r) {
            float a = acc[r] + bb_in;
            float gl = 0.5f * a * (1.f + erff(a * is2));
            hT[lane][half * 64 + r0 + r] = f2tf32(gl);
        }
    }

    __syncthreads();
    for (int i = tid; i < 32 * 128; i += 256) {
        int k = i >> 7, c = i & 127;
        BT[k][c] = f2tf32(Wl[i]);
    }
    __syncthreads();

    int g = lane >> 2, tig = lane & 3;
    int warp_m = warp & 3, warp_n = warp >> 2;

    for (int pass = 0; pass < 2; ++pass) {
        float macc[2][8][4];
        #pragma unroll
        for (int mt = 0; mt < 2; ++mt)
            #pragma unroll
            for (int nt = 0; nt < 8; ++nt)
                #pragma unroll
                for (int q = 0; q < 4; ++q) macc[mt][nt][q] = 0.f;

        #pragma unroll
        for (int ks = 0; ks < 4; ++ks) {
            int kb = ks * 8;
            unsigned af[2][4];
            #pragma unroll
            for (int mt = 0; mt < 2; ++mt) {
                int mr = warp_m * 32 + mt * 16;
                af[mt][0] = __float_as_uint(hT[kb + tig    ][mr + g]);
                af[mt][1] = __float_as_uint(hT[kb + tig    ][mr + g + 8]);
                af[mt][2] = __float_as_uint(hT[kb + tig + 4][mr + g]);
                af[mt][3] = __float_as_uint(hT[kb + tig + 4][mr + g + 8]);
            }
            #pragma unroll
            for (int nt = 0; nt < 8; ++nt) {
                int nc = warp_n * 64 + nt * 8;
                unsigned bf0 = __float_as_uint(BT[kb + tig    ][nc + g]);
                unsigned bf1 = __float_as_uint(BT[kb + tig + 4][nc + g]);
                #pragma unroll
                for (int mt = 0; mt < 2; ++mt) {
                    asm volatile(
                        "mma.sync.aligned.m16n8k8.row.col.f32.tf32.tf32.f32 "
                        "{%0,%1,%2,%3}, {%4,%5,%6,%7}, {%8,%9}, {%0,%1,%2,%3};"
                        : "+f"(macc[mt][nt][0]), "+f"(macc[mt][nt][1]),
                          "+f"(macc[mt][nt][2]), "+f"(macc[mt][nt][3])
                        : "r"(af[mt][0]), "r"(af[mt][1]), "r"(af[mt][2]), "r"(af[mt][3]),
                          "r"(bf0), "r"(bf1));
                }
            }
        }

        const float* bias = pass ? br : bl;
        #pragma unroll
        for (int nt = 0; nt < 8; ++nt) {
            int col = warp_n * 64 + nt * 8 + 2 * tig;
            float2 bb = *reinterpret_cast<const float2*>(&bias[col]);
            #pragma unroll
            for (int mt = 0; mt < 2; ++mt) {
                int row_a = node0 + warp_m * 32 + mt * 16 + g;
                int row_b = row_a + 8;
                float c0 = macc[mt][nt][0] + bb.x;
                float c1 = macc[mt][nt][1] + bb.y;
                float c2 = macc[mt][nt][2] + bb.x;
                float c3 = macc[mt][nt][3] + bb.y;
                if (pass == 0) {
                    if (row_a < n)
                        *reinterpret_cast<float2*>(&xl_out[(size_t)row_a * 128 + col]) = make_float2(c0, c1);
                    if (row_b < n)
                        *reinterpret_cast<float2*>(&xl_out[(size_t)row_b * 128 + col]) = make_float2(c2, c3);
                } else {
                    if (row_a < n) g_xrh[(size_t)row_a * 64 + (col >> 1)] = __floats2half2_rn(c0, c1);
                    if (row_b < n) g_xrh[(size_t)row_b * 64 + (col >> 1)] = __floats2half2_rn(c2, c3);
                }
            }
        }
        if (pass == 0) {
            __syncthreads();
            for (int i = tid; i < 32 * 128; i += 256) {
                int k = i >> 7, c = i & 127;
                BT[k][c] = f2tf32(Wr[i]);
            }
            __syncthreads();
        }
    }
}

// ---------------- TF32 tensor-core GEMM (dual): xl/xr, K=128 layers ----
__global__ __launch_bounds__(256) void gemm_mma(
    const float* __restrict__ A,
    const float* __restrict__ W0, const float* __restrict__ b0, float* __restrict__ C0,
    const float* __restrict__ W1, const float* __restrict__ b1,
    int n, int K)
{
    const float* W    = blockIdx.y ? W1 : W0;
    const float* bias = blockIdx.y ? b1 : b0;

    __shared__ float As[2][16][136];   // [k][m]
    __shared__ float Ws[2][16][136];   // [k][n]
    int tid  = threadIdx.x;
    int warp = tid >> 5, lane = tid & 31;
    int g    = lane >> 2, tig = lane & 3;
    int warp_m = warp & 3, warp_n = warp >> 2;
    int row0 = blockIdx.x * 128;

    float acc[2][8][4];
    #pragma unroll
    for (int mt = 0; mt < 2; ++mt)
        #pragma unroll
        for (int nt = 0; nt < 8; ++nt)
            #pragma unroll
            for (int q = 0; q < 4; ++q) acc[mt][nt][q] = 0.f;

    int chunks = K >> 4;
    float4 ra[2], rw[2];

    #pragma unroll
    for (int j = 0; j < 2; ++j) {
        int idx = tid * 2 + j;
        int r = idx >> 2, k4 = idx & 3;
        ra[j] = *reinterpret_cast<const float4*>(&A[(size_t)(row0 + r) * K + k4 * 4]);
        int k = idx >> 5, c4 = idx & 31;
        rw[j] = *reinterpret_cast<const float4*>(&W[(size_t)k * 128 + c4 * 4]);
    }
    #pragma unroll
    for (int j = 0; j < 2; ++j) {
        int idx = tid * 2 + j;
        int r = idx >> 2, k4 = idx & 3;
        As[0][k4 * 4 + 0][r] = f2tf32(ra[j].x);
        As[0][k4 * 4 + 1][r] = f2tf32(ra[j].y);
        As[0][k4 * 4 + 2][r] = f2tf32(ra[j].z);
        As[0][k4 * 4 + 3][r] = f2tf32(ra[j].w);
        int k = idx >> 5, c4 = idx & 31;
        Ws[0][k][c4 * 4 + 0] = f2tf32(rw[j].x);
        Ws[0][k][c4 * 4 + 1] = f2tf32(rw[j].y);
        Ws[0][k][c4 * 4 + 2] = f2tf32(rw[j].z);
        Ws[0][k][c4 * 4 + 3] = f2tf32(rw[j].w);
    }
    __syncthreads();

    for (int c = 0; c < chunks; ++c) {
        int buf = c & 1;
        if (c + 1 < chunks) {
            int kc = (c + 1) * 16;
            #pragma unroll
            for (int j = 0; j < 2; ++j) {
                int idx = tid * 2 + j;
                int r = idx >> 2, k4 = idx & 3;
                ra[j] = *reinterpret_cast<const float4*>(&A[(size_t)(row0 + r) * K + kc + k4 * 4]);
                int k = idx >> 5, c4 = idx & 31;
                rw[j] = *reinterpret_cast<const float4*>(&W[(size_t)(kc + k) * 128 + c4 * 4]);
            }
        }
        #pragma unroll
        for (int ks = 0; ks < 2; ++ks) {
            int kb = ks * 8;
            unsigned af[2][4];
            #pragma unroll
            for (int mt = 0; mt < 2; ++mt) {
                int mr = warp_m * 32 + mt * 16;
                af[mt][0] = __float_as_uint(As[buf][kb + tig    ][mr + g]);
                af[mt][1] = __float_as_uint(As[buf][kb + tig    ][mr + g + 8]);
                af[mt][2] = __float_as_uint(As[buf][kb + tig + 4][mr + g]);
                af[mt][3] = __float_as_uint(As[buf][kb + tig + 4][mr + g + 8]);
            }
            #pragma unroll
            for (int nt = 0; nt < 8; ++nt) {
                int nc = warp_n * 64 + nt * 8;
                unsigned bf0 = __float_as_uint(Ws[buf][kb + tig    ][nc + g]);
                unsigned bf1 = __float_as_uint(Ws[buf][kb + tig + 4][nc + g]);
                #pragma unroll
                for (int mt = 0; mt < 2; ++mt) {
                    asm volatile(
                        "mma.sync.aligned.m16n8k8.row.col.f32.tf32.tf32.f32 "
                        "{%0,%1,%2,%3}, {%4,%5,%6,%7}, {%8,%9}, {%0,%1,%2,%3};"
                        : "+f"(acc[mt][nt][0]), "+f"(acc[mt][nt][1]),
                          "+f"(acc[mt][nt][2]), "+f"(acc[mt][nt][3])
                        : "r"(af[mt][0]), "r"(af[mt][1]), "r"(af[mt][2]), "r"(af[mt][3]),
                          "r"(bf0), "r"(bf1));
                }
            }
        }
        if (c + 1 < chunks) {
            int nb = buf ^ 1;
            #pragma unroll
            for (int j = 0; j < 2; ++j) {
                int idx = tid * 2 + j;
                int r = idx >> 2, k4 = idx & 3;
                As[nb][k4 * 4 + 0][r] = f2tf32(ra[j].x);
                As[nb][k4 * 4 + 1][r] = f2tf32(ra[j].y);
                As[nb][k4 * 4 + 2][r] = f2tf32(ra[j].z);
                As[nb][k4 * 4 + 3][r] = f2tf32(ra[j].w);
                int k = idx >> 5, c4 = idx & 31;
                Ws[nb][k][c4 * 4 + 0] = f2tf32(rw[j].x);
                Ws[nb][k][c4 * 4 + 1] = f2tf32(rw[j].y);
                Ws[nb][k][c4 * 4 + 2] = f2tf32(rw[j].z);
                Ws[nb][k][c4 * 4 + 3] = f2tf32(rw[j].w);
            }
        }
        __syncthreads();
    }

    int wantxl = (blockIdx.y == 0);
    #pragma unroll
    for (int nt = 0; nt < 8; ++nt) {
        int col = warp_n * 64 + nt * 8 + 2 * tig;
        float2 bb = *reinterpret_cast<const float2*>(&bias[col]);
        #pragma unroll
        for (int mt = 0; mt < 2; ++mt) {
            int row_a = row0 + warp_m * 32 + mt * 16 + g;
            int row_b = row_a + 8;
            float c0 = acc[mt][nt][0] + bb.x;
            float c1 = acc[mt][nt][1] + bb.y;
            float c2 = acc[mt][nt][2] + bb.x;
            float c3 = acc[mt][nt][3] + bb.y;
            if (wantxl) {
                if (row_a < n)
                    *reinterpret_cast<float2*>(&C0[(size_t)row_a * 128 + col]) = make_float2(c0, c1);
                if (row_b < n)
                    *reinterpret_cast<float2*>(&C0[(size_t)row_b * 128 + col]) = make_float2(c2, c3);
            } else {
                if (row_a < n)
                    g_xrh[(size_t)row_a * 64 + (col >> 1)] = __floats2half2_rn(c0, c1);
                if (row_b < n)
                    g_xrh[(size_t)row_b * 64 + (col >> 1)] = __floats2half2_rn(c2, c3);
            }
        }
    }
}

// ---------------- TF32 mma final projection with fused row L2 norm ----
__global__ __launch_bounds__(256) void gemm_out_mma(
    const float* __restrict__ A,
    const float* __restrict__ W, const float* __restrict__ bias,
    float* __restrict__ C, int n)
{
    __shared__ float As[2][16][136];
    __shared__ float Ws[2][16][136];
    __shared__ float rsum[128][2];
    const int K = 128;
    int tid  = threadIdx.x;
    int warp = tid >> 5, lane = tid & 31;
    int g    = lane >> 2, tig = lane & 3;
    int warp_m = warp & 3, warp_n = warp >> 2;
    int row0 = blockIdx.x * 128;

    float acc[2][8][4];
    #pragma unroll
    for (int mt = 0; mt < 2; ++mt)
        #pragma unroll
        for (int nt = 0; nt < 8; ++nt)
            #pragma unroll
            for (int q = 0; q < 4; ++q) acc[mt][nt][q] = 0.f;

    int chunks = K >> 4;
    float4 ra[2], rw[2];
    #pragma unroll
    for (int j = 0; j < 2; ++j) {
        int idx = tid * 2 + j;
        int r = idx >> 2, k4 = idx & 3;
        ra[j] = *reinterpret_cast<const float4*>(&A[(size_t)(row0 + r) * K + k4 * 4]);
        int k = idx >> 5, c4 = idx & 31;
        rw[j] = *reinterpret_cast<const float4*>(&W[(size_t)k * 128 + c4 * 4]);
    }
    #pragma unroll
    for (int j = 0; j < 2; ++j) {
        int idx = tid * 2 + j;
        int r = idx >> 2, k4 = idx & 3;
        As[0][k4 * 4 + 0][r] = f2tf32(ra[j].x);
        As[0][k4 * 4 + 1][r] = f2tf32(ra[j].y);
        As[0][k4 * 4 + 2][r] = f2tf32(ra[j].z);
        As[0][k4 * 4 + 3][r] = f2tf32(ra[j].w);
        int k = idx >> 5, c4 = idx & 31;
        Ws[0][k][c4 * 4 + 0] = f2tf32(rw[j].x);
        Ws[0][k][c4 * 4 + 1] = f2tf32(rw[j].y);
        Ws[0][k][c4 * 4 + 2] = f2tf32(rw[j].z);
        Ws[0][k][c4 * 4 + 3] = f2tf32(rw[j].w);
    }
    __syncthreads();

    for (int c = 0; c < chunks; ++c) {
        int buf = c & 1;
        if (c + 1 < chunks) {
            int kc = (c + 1) * 16;
            #pragma unroll
            for (int j = 0; j < 2; ++j) {
                int idx = tid * 2 + j;
                int r = idx >> 2, k4 = idx & 3;
                ra[j] = *reinterpret_cast<const float4*>(&A[(size_t)(row0 + r) * K + kc + k4 * 4]);
                int k = idx >> 5, c4 = idx & 31;
                rw[j] = *reinterpret_cast<const float4*>(&W[(size_t)(kc + k) * 128 + c4 * 4]);
            }
        }
        #pragma unroll
        for (int ks = 0; ks < 2; ++ks) {
            int kb = ks * 8;
            unsigned af[2][4];
            #pragma unroll
            for (int mt = 0; mt < 2; ++mt) {
                int mr = warp_m * 32 + mt * 16;
                af[mt][0] = __float_as_uint(As[buf][kb + tig    ][mr + g]);
                af[mt][1] = __float_as_uint(As[buf][kb + tig    ][mr + g + 8]);
                af[mt][2] = __float_as_uint(As[buf][kb + tig + 4][mr + g]);
                af[mt][3] = __float_as_uint(As[buf][kb + tig + 4][mr + g + 8]);
            }
            #pragma unroll
            for (int nt = 0; nt < 8; ++nt) {
                int nc = warp_n * 64 + nt * 8;
                unsigned bf0 = __float_as_uint(Ws[buf][kb + tig    ][nc + g]);
                unsigned bf1 = __float_as_uint(Ws[buf][kb + tig + 4][nc + g]);
                #pragma unroll
                for (int mt = 0; mt < 2; ++mt) {
                    asm volatile(
                        "mma.sync.aligned.m16n8k8.row.col.f32.tf32.tf32.f32 "
                        "{%0,%1,%2,%3}, {%4,%5,%6,%7}, {%8,%9}, {%0,%1,%2,%3};"
                        : "+f"(acc[mt][nt][0]), "+f"(acc[mt][nt][1]),
                          "+f"(acc[mt][nt][2]), "+f"(acc[mt][nt][3])
                        : "r"(af[mt][0]), "r"(af[mt][1]), "r"(af[mt][2]), "r"(af[mt][3]),
                          "r"(bf0), "r"(bf1));
                }
            }
        }
        if (c + 1 < chunks) {
            int nb = buf ^ 1;
            #pragma unroll
            for (int j = 0; j < 2; ++j) {
                int idx = tid * 2 + j;
                int r = idx >> 2, k4 = idx & 3;
                As[nb][k4 * 4 + 0][r] = f2tf32(ra[j].x);
                As[nb][k4 * 4 + 1][r] = f2tf32(ra[j].y);
                As[nb][k4 * 4 + 2][r] = f2tf32(ra[j].z);
                As[nb][k4 * 4 + 3][r] = f2tf32(ra[j].w);
                int k = idx >> 5, c4 = idx & 31;
                Ws[nb][k][c4 * 4 + 0] = f2tf32(rw[j].x);
                Ws[nb][k][c4 * 4 + 1] = f2tf32(rw[j].y);
                Ws[nb][k][c4 * 4 + 2] = f2tf32(rw[j].z);
                Ws[nb][k][c4 * 4 + 3] = f2tf32(rw[j].w);
            }
        }
        __syncthreads();
    }

    float sa[2] = {0.f, 0.f}, sb[2] = {0.f, 0.f};
    #pragma unroll
    for (int nt = 0; nt < 8; ++nt) {
        int col = warp_n * 64 + nt * 8 + 2 * tig;
        float2 bb = *reinterpret_cast<const float2*>(&bias[col]);
        #pragma unroll
        for (int mt = 0; mt < 2; ++mt) {
            acc[mt][nt][0] += bb.x;
            acc[mt][nt][1] += bb.y;
            acc[mt][nt][2] += bb.x;
            acc[mt][nt][3] += bb.y;
            sa[mt] = fmaf(acc[mt][nt][0], acc[mt][nt][0], fmaf(acc[mt][nt][1], acc[mt][nt][1], sa[mt]));
            sb[mt] = fmaf(acc[mt][nt][2], acc[mt][nt][2], fmaf(acc[mt][nt][3], acc[mt][nt][3], sb[mt]));
        }
    }
    #pragma unroll
    for (int mt = 0; mt < 2; ++mt) {
        sa[mt] += __shfl_xor_sync(0xffffffffu, sa[mt], 1);
        sa[mt] += __shfl_xor_sync(0xffffffffu, sa[mt], 2);
        sb[mt] += __shfl_xor_sync(0xffffffffu, sb[mt], 1);
        sb[mt] += __shfl_xor_sync(0xffffffffu, sb[mt], 2);
        if (tig == 0) {
            int rla = warp_m * 32 + mt * 16 + g;
            rsum[rla][warp_n]     = sa[mt];
            rsum[rla + 8][warp_n] = sb[mt];
        }
    }
    __syncthreads();
    #pragma unroll
    for (int mt = 0; mt < 2; ++mt) {
        int rla = warp_m * 32 + mt * 16 + g;
        float inva = 1.f / fmaxf(sqrtf(rsum[rla][0]     + rsum[rla][1]),     1e-12f);
        float invb = 1.f / fmaxf(sqrtf(rsum[rla + 8][0] + rsum[rla + 8][1]), 1e-12f);
        int row_a = row0 + rla;
        int row_b = row_a + 8;
        #pragma unroll
        for (int nt = 0; nt < 8; ++nt) {
            int col = warp_n * 64 + nt * 8 + 2 * tig;
            if (row_a < n)
                *reinterpret_cast<float2*>(&C[(size_t)row_a * 128 + col]) =
                    make_float2(acc[mt][nt][0] * inva, acc[mt][nt][1] * inva);
            if (row_b < n)
                *reinterpret_cast<float2*>(&C[(size_t)row_b * 128 + col]) =
                    make_float2(acc[mt][nt][2] * invb, acc[mt][nt][3] * invb);
        }
    }
}

// ---------------- fused GATv2 aggregation + LayerNorm + GELU + residual
// ONE WARP per node; dual-dot logit (exact identity); 3-step shfl reduce.
__global__ __launch_bounds__(256) void gat_agg(
    const float* __restrict__ att, const float* __restrict__ bo,
    const float* __restrict__ gam, const float* __restrict__ bet,
    int resflag, int n)
{
    int warp = threadIdx.x >> 5;
    int lane = threadIdx.x & 31;
    int i = blockIdx.x * 8 + warp;
    if (i >= n) return;
    int c0 = lane * 4;

    float4 xl = *reinterpret_cast<const float4*>(&g_xl[(size_t)i * 128 + c0]);
    float4 a4 = __ldg(reinterpret_cast<const float4*>(&att[c0]));

#define GAT_LOGIT(vv, xv)                                                    \
    {                                                                        \
        float s0 = xl.x + xv.x;                                              \
        float s1 = xl.y + xv.y;                                              \
        float s2 = xl.z + xv.z;                                              \
        float s3 = xl.w + xv.w;                                              \
        float dA = s0 * a4.x;                                                \
        dA = fmaf(s1, a4.y, dA);                                             \
        dA = fmaf(s2, a4.z, dA);                                             \
        dA = fmaf(s3, a4.w, dA);                                             \
        float dB = fabsf(s0) * a4.x;                                         \
        dB = fmaf(fabsf(s1), a4.y, dB);                                      \
        dB = fmaf(fabsf(s2), a4.z, dB);                                      \
        dB = fmaf(fabsf(s3), a4.w, dB);                                      \
        vv = fmaf(0.4f, dB, 0.6f * dA);                                      \
    }

    // self loop first
    float4 xs = ldxr_h(i, lane);
    float v;
    GAT_LOGIT(v, xs);
    v += __shfl_xor_sync(0xffffffffu, v, 1);
    v += __shfl_xor_sync(0xffffffffu, v, 2);
    v += __shfl_xor_sync(0xffffffffu, v, 4);
    float m = v, den = 1.f;
    float4 acc = xs;

#define GAT_RUNMERGE(vv, xv)                                                 \
    {                                                                        \
        float nm = fmaxf(m, vv);                                             \
        float sc = __expf(m - nm);                                           \
        float pe = __expf(vv - nm);                                          \
        den = fmaf(den, sc, pe);                                             \
        acc.x = fmaf(acc.x, sc, pe * xv.x);                                  \
        acc.y = fmaf(acc.y, sc, pe * xv.y);                                  \
        acc.z = fmaf(acc.z, sc, pe * xv.z);                                  \
        acc.w = fmaf(acc.w, sc, pe * xv.w);                                  \
        m = nm;                                                              \
    }

#define GAT_BODY4(xa, xb, xc, xd)                                            \
    {                                                                        \
        float va, vb, vc, vd;                                                \
        GAT_LOGIT(va, xa);                                                   \
        GAT_LOGIT(vb, xb);                                                   \
        GAT_LOGIT(vc, xc);                                                   \
        GAT_LOGIT(vd, xd);                                                   \
        va += __shfl_xor_sync(0xffffffffu, va, 1);                           \
        vb += __shfl_xor_sync(0xffffffffu, vb, 1);                           \
        vc += __shfl_xor_sync(0xffffffffu, vc, 1);                           \
        vd += __shfl_xor_sync(0xffffffffu, vd, 1);                           \
        va += __shfl_xor_sync(0xffffffffu, va, 2);                           \
        vb += __shfl_xor_sync(0xffffffffu, vb, 2);                           \
        vc += __shfl_xor_sync(0xffffffffu, vc, 2);                           \
        vd += __shfl_xor_sync(0xffffffffu, vd, 2);                           \
        va += __shfl_xor_sync(0xffffffffu, va, 4);                           \
        vb += __shfl_xor_sync(0xffffffffu, vb, 4);                           \
        vc += __shfl_xor_sync(0xffffffffu, vc, 4);                           \
        vd += __shfl_xor_sync(0xffffffffu, vd, 4);                           \
        float mab = fmaxf(va, vb);                                           \
        float pa  = __expf(va - mab);                                        \
        float pb  = __expf(vb - mab);                                        \
        float dab = pa + pb;                                                 \
        float4 aab;                                                          \
        aab.x = fmaf(pa, xa.x, pb * xb.x);                                   \
        aab.y = fmaf(pa, xa.y, pb * xb.y);                                   \
        aab.z = fmaf(pa, xa.z, pb * xb.z);                                   \
        aab.w = fmaf(pa, xa.w, pb * xb.w);                                   \
        float mcd = fmaxf(vc, vd);                                           \
        float pc  = __expf(vc - mcd);                                        \
        float pd  = __expf(vd - mcd);                                        \
        float dcd = pc + pd;                                                 \
        float4 acd;                                                          \
        acd.x = fmaf(pc, xc.x, pd * xd.x);                                   \
        acd.y = fmaf(pc, xc.y, pd * xd.y);                                   \
        acd.z = fmaf(pc, xc.z, pd * xd.z);                                   \
        acd.w = fmaf(pc, xc.w, pd * xd.w);                                   \
        {                                                                    \
            float nm = fmaxf(m, mab);                                        \
            float sc = __expf(m - nm);                                       \
            float s2 = __expf(mab - nm);                                     \
            den = fmaf(den, sc, dab * s2);                                   \
            acc.x = fmaf(acc.x, sc, aab.x * s2);                             \
            acc.y = fmaf(acc.y, sc, aab.y * s2);                             \
            acc.z = fmaf(acc.z, sc, aab.z * s2);                             \
            acc.w = fmaf(acc.w, sc, aab.w * s2);                             \
            m = nm;                                                          \
        }                                                                    \
        {                                                                    \
            float nm = fmaxf(m, mcd);                                        \
            float sc = __expf(m - nm);                                       \
            float s2 = __expf(mcd - nm);                                     \
            den = fmaf(den, sc, dcd * s2);                                   \
            acc.x = fmaf(acc.x, sc, acd.x * s2);                             \
            acc.y = fmaf(acc.y, sc, acd.y * s2);                             \
            acc.z = fmaf(acc.z, sc, acd.z * s2);                             \
            acc.w = fmaf(acc.w, sc, acd.w * s2);                             \
            m = nm;                                                          \
        }                                                                    \
    }

    int beg = g_rowptr[i], end = g_rowptr[i + 1];
    int k = beg;

    float4 pxa, pxb, pxc, pxd;
    if (k + 4 <= end) {
        pxa = ldxr_h(g_col[k], lane);
        pxb = ldxr_h(g_col[k + 1], lane);
        pxc = ldxr_h(g_col[k + 2], lane);
        pxd = ldxr_h(g_col[k + 3], lane);
    }
    for (; k + 8 <= end; k += 4) {
        float4 nxa = ldxr_h(g_col[k + 4], lane);
        float4 nxb = ldxr_h(g_col[k + 5], lane);
        float4 nxc = ldxr_h(g_col[k + 6], lane);
        float4 nxd = ldxr_h(g_col[k + 7], lane);
        GAT_BODY4(pxa, pxb, pxc, pxd);
        pxa = nxa; pxb = nxb; pxc = nxc; pxd = nxd;
    }
    if (k + 4 <= end) {
        GAT_BODY4(pxa, pxb, pxc, pxd);
        k += 4;
    }
    if (k + 2 <= end) {
        float4 xa = ldxr_h(g_col[k], lane);
        float4 xb = ldxr_h(g_col[k + 1], lane);
        float va, vb;
        GAT_LOGIT(va, xa);
        GAT_LOGIT(vb, xb);
        va += __shfl_xor_sync(0xffffffffu, va, 1);
        vb += __shfl_xor_sync(0xffffffffu, vb, 1);
        va += __shfl_xor_sync(0xffffffffu, va, 2);
        vb += __shfl_xor_sync(0xffffffffu, vb, 2);
        va += __shfl_xor_sync(0xffffffffu, va, 4);
        vb += __shfl_xor_sync(0xffffffffu, vb, 4);
        GAT_RUNMERGE(va, xa);
        GAT_RUNMERGE(vb, xb);
        k += 2;
    }
    if (k < end) {
        float4 xa = ldxr_h(g_col[k], lane);
        float va;
        GAT_LOGIT(va, xa);
        va += __shfl_xor_sync(0xffffffffu, va, 1);
        va += __shfl_xor_sync(0xffffffffu, va, 2);
        va += __shfl_xor_sync(0xffffffffu, va, 4);
        GAT_RUNMERGE(va, xa);
    }
#undef GAT_LOGIT
#undef GAT_RUNMERGE
#undef GAT_BODY4

    float inv = 1.f / (den + 1e-16f);
    float4 bo4 = __ldg(reinterpret_cast<const float4*>(&bo[c0]));
    float o0 = fmaf(acc.x, inv, bo4.x);
    float o1 = fmaf(acc.y, inv, bo4.y);
    float o2 = fmaf(acc.z, inv, bo4.z);
    float o3 = fmaf(acc.w, inv, bo4.w);

    float s1 = o0 + o1 + o2 + o3;
    float s2 = fmaf(o0, o0, fmaf(o1, o1, fmaf(o2, o2, o3 * o3)));
    #pragma unroll
    for (int o = 1; o < 32; o <<= 1) {
        s1 += __shfl_xor_sync(0xffffffffu, s1, o);
        s2 += __shfl_xor_sync(0xffffffffu, s2, o);
    }
    float mu  = s1 * (1.f / 128.f);
    float var = s2 * (1.f / 128.f) - mu * mu;
    var = var > 0.f ? var : 0.f;
    float rstd = rsqrtf(var + 1e-5f);
    float4 g4 = __ldg(reinterpret_cast<const float4*>(&gam[c0]));
    float4 b4 = __ldg(reinterpret_cast<const float4*>(&bet[c0]));
    float y0 = g4.x * (o0 - mu) * rstd + b4.x;
    float y1 = g4.y * (o1 - mu) * rstd + b4.y;
    float y2 = g4.z * (o2 - mu) * rstd + b4.z;
    float y3 = g4.w * (o3 - mu) * rstd + b4.w;
    const float is2 = 0.70710678118654752f;
    float gl0 = 0.5f * y0 * (1.f + erff(y0 * is2));
    float gl1 = 0.5f * y1 * (1.f + erff(y1 * is2));
    float gl2 = 0.5f * y2 * (1.f + erff(y2 * is2));
    float gl3 = 0.5f * y3 * (1.f + erff(y3 * is2));

    float4* hp = reinterpret_cast<float4*>(&g_h[(size_t)i * 128 + c0]);
    if (resflag) {
        float4 hv = *hp;
        hv.x += gl0; hv.y += gl1; hv.z += gl2; hv.w += gl3;
        *hp = hv;
    } else {
        *hp = make_float4(gl0, gl1, gl2, gl3);
    }
}

// ---------------- host launcher ----------------
extern "C" void kernel_launch(void* const* d_in, const int* in_sizes, int n_in,
                              void* d_out, int out_size)
{
    const float* x    = (const float*)d_in[0];
    const void*  ei   = d_in[1];
    const float* W_in = (const float*)d_in[2];
    const float* b_in = (const float*)d_in[3];
    const float *Wl[3], *bl[3], *Wr[3], *br[3], *att[3], *bo[3], *gg[3], *be[3];
    for (int l = 0; l < 3; ++l) {
        int base = 4 + l * 8;
        Wl[l]  = (const float*)d_in[base + 0];
        bl[l]  = (const float*)d_in[base + 1];
        Wr[l]  = (const float*)d_in[base + 2];
        br[l]  = (const float*)d_in[base + 3];
        att[l] = (const float*)d_in[base + 4];
        bo[l]  = (const float*)d_in[base + 5];
        gg[l]  = (const float*)d_in[base + 6];
        be[l]  = (const float*)d_in[base + 7];
    }
    const float* W_out = (const float*)d_in[28];
    const float* b_out = (const float*)d_in[29];

    int n = in_sizes[0] / 128;
    int e = in_sizes[1] / 2;
    int P = (n + 1023) / 1024;

    float *hbuf, *xlbuf;
    cudaGetSymbolAddress((void**)&hbuf,  g_h);
    cudaGetSymbolAddress((void**)&xlbuf, g_xl);

    static int inited = 0;
    static cudaStream_t s2;
    static cudaEvent_t ev_fork, ev_join;
    if (!inited) {
        cudaFuncSetAttribute(fused_in_l0,
                             cudaFuncAttributeMaxDynamicSharedMemorySize, FUSED_SMEM);
        cudaStreamCreateWithFlags(&s2, cudaStreamNonBlocking);
        cudaEventCreateWithFlags(&ev_fork, cudaEventDisableTiming);
        cudaEventCreateWithFlags(&ev_join, cudaEventDisableTiming);
        inited = 1;
    }

    dim3 gdual((n + 127) / 128, 2);
    int gsingle = (n + 127) / 128;
    int aggblocks = (n + 7) / 8;

    // fork: CSR chain on s2, concurrent with fused_in_l0 on main stream
    cudaEventRecord(ev_fork, 0);
    cudaStreamWaitEvent(s2, ev_fork, 0);

    zero_detect<<<(n + 255) / 256, 256, 0, s2>>>(ei, e, n);
    convert_hist<<<(e + 255) / 256, 256, 0, s2>>>(ei, e);
    scan_part<<<P, 256, 0, s2>>>(n);
    scan_down<<<P, 256, 0, s2>>>(n, P);
    scatter_edges<<<(e + 255) / 256, 256, 0, s2>>>(e);
    sort_warp<<<(n + 7) / 8, 256, 0, s2>>>(n);
    cudaEventRecord(ev_join, s2);

    fused_in_l0<<<gsingle, 256, FUSED_SMEM>>>(x, W_in, b_in,
                                              Wl[0], bl[0], Wr[0], br[0],
                                              xlbuf, n);

    // join: gat needs both CSR and xl/xr
    cudaStreamWaitEvent(0, ev_join, 0);

    gat_agg<<<aggblocks, 256>>>(att[0], bo[0], gg[0], be[0], 0, n);
    for (int l = 1; l < 3; ++l) {
        gemm_mma<<<gdual, 256>>>(hbuf, Wl[l], bl[l], xlbuf, Wr[l], br[l], n, 128);
        gat_agg<<<aggblocks, 256>>>(att[l], bo[l], gg[l], be[l], 1, n);
    }

    gemm_out_mma<<<gsingle, 256>>>(hbuf, W_out, b_out, (float*)d_out, n);
}